// round 2
// baseline (speedup 1.0000x reference)
#include <cuda_runtime.h>

#define HH 128
#define WW 128
#define TY 16   // output rows per thread (streamed)

// Depthwise 4x4 blur (upfirdn2d pad=(2,1)), separable rank-1 kernel.
// out[y] = vk0*h[y-2] + vk1*h[y-1] + vk2*h[y] + vk3*h[y+1]
// h[x]   = hk0*in[x-2] + hk1*in[x-1] + hk2*in[x] + hk3*in[x+1]
// Halos in x come from neighbor lanes via warp shuffle (warp = one full row).
__global__ __launch_bounds__(256) void blur_kernel(
    const float* __restrict__ x,
    const float* __restrict__ ker,
    float* __restrict__ out)
{
    const int plane = blockIdx.x;                 // one (n,c) plane per block
    const int lane  = threadIdx.x;                // 0..31, x-quad index
    const int x0    = lane * 4;
    const int y0    = threadIdx.y * TY;           // 8 strips of 16 rows

    // ---- factorize 4x4 kernel (rank-1): c[b]=K[0][b], r[a]=K[a][0]/K[0][0]
    const float c0 = __ldg(ker + 0), c1 = __ldg(ker + 1);
    const float c2 = __ldg(ker + 2), c3 = __ldg(ker + 3);
    const float inv = 1.0f / c0;
    const float r1 = __ldg(ker + 4)  * inv;
    const float r2 = __ldg(ker + 8)  * inv;
    const float r3 = __ldg(ker + 12) * inv;
    // flipped taps
    const float hk0 = c3, hk1 = c2, hk2 = c1, hk3 = c0;
    const float vk0 = r3, vk1 = r2, vk2 = r1;     // vk3 == 1.0f

    const float* __restrict__ p = x   + (size_t)plane * (HH * WW);
    float*       __restrict__ q = out + (size_t)plane * (HH * WW) + y0 * WW + x0;

    // load one input row (zero outside), horizontal pass with shuffled halos
    auto hrow = [&](int r) -> float4 {
        float4 M = make_float4(0.f, 0.f, 0.f, 0.f);
        if (r >= 0 && r < HH)                               // warp-uniform predicate
            M = *reinterpret_cast<const float4*>(p + r * WW + x0);
        float lm2 = __shfl_up_sync(0xffffffffu, M.z, 1);    // in[x0-2]
        float lm1 = __shfl_up_sync(0xffffffffu, M.w, 1);    // in[x0-1]
        float rp0 = __shfl_down_sync(0xffffffffu, M.x, 1);  // in[x0+4]
        if (lane == 0)  { lm2 = 0.f; lm1 = 0.f; }           // left pad = 2 zeros
        if (lane == 31) { rp0 = 0.f; }                      // right pad = 1 zero
        float4 h;
        h.x = fmaf(lm2, hk0, fmaf(lm1, hk1, fmaf(M.x, hk2, M.y * hk3)));
        h.y = fmaf(lm1, hk0, fmaf(M.x, hk1, fmaf(M.y, hk2, M.z * hk3)));
        h.z = fmaf(M.x, hk0, fmaf(M.y, hk1, fmaf(M.z, hk2, M.w * hk3)));
        h.w = fmaf(M.y, hk0, fmaf(M.z, hk1, fmaf(M.w, hk2, rp0 * hk3)));
        return h;
    };

    // rolling 4-row h window, emit one output row per new input row
    float4 h0 = hrow(y0 - 2);
    float4 h1 = hrow(y0 - 1);
    float4 h2 = hrow(y0);

    #pragma unroll
    for (int k = 0; k < TY; ++k) {
        float4 h3 = hrow(y0 + 1 + k);
        float4 a;
        a.x = fmaf(h0.x, vk0, fmaf(h1.x, vk1, fmaf(h2.x, vk2, h3.x)));
        a.y = fmaf(h0.y, vk0, fmaf(h1.y, vk1, fmaf(h2.y, vk2, h3.y)));
        a.z = fmaf(h0.z, vk0, fmaf(h1.z, vk1, fmaf(h2.z, vk2, h3.z)));
        a.w = fmaf(h0.w, vk0, fmaf(h1.w, vk1, fmaf(h2.w, vk2, h3.w)));
        *reinterpret_cast<float4*>(q + k * WW) = a;
        h0 = h1; h1 = h2; h2 = h3;
    }
}

extern "C" void kernel_launch(void* const* d_in, const int* in_sizes, int n_in,
                              void* d_out, int out_size)
{
    const float* x   = (const float*)d_in[0];
    const float* ker = (const float*)d_in[1];
    float*       out = (float*)d_out;

    const int planes = in_sizes[0] / (HH * WW);   // 8*256 = 2048
    dim3 block(32, HH / TY);                      // 32 x-lanes, 8 y-strips = 256 thr
    dim3 grid(planes);                            // one plane per block
    blur_kernel<<<grid, block>>>(x, ker, out);
}

// round 3
// speedup vs baseline: 1.0874x; 1.0874x over previous
#include <cuda_runtime.h>

#define HH 128
#define WW 128
#define TY 8    // output rows per thread (streamed)

// Depthwise 4x4 blur (upfirdn2d pad=(2,1)), separable rank-1 kernel.
// out[y] = vk0*h[y-2] + vk1*h[y-1] + vk2*h[y] + vk3*h[y+1]
// h[x]   = hk0*in[x-2] + hk1*in[x-1] + hk2*in[x] + hk3*in[x+1]
// Halos loaded directly (independent LDGs, L1-served) — no shuffles, no smem.
__global__ __launch_bounds__(256) void blur_kernel(
    const float* __restrict__ x,
    const float* __restrict__ ker,
    float* __restrict__ out)
{
    const int plane = blockIdx.y;                       // (n,c) plane
    const int y0 = blockIdx.x * 64 + threadIdx.y * TY;  // 8-row output strip
    const int x0 = threadIdx.x * 4;                     // 4-col output block

    // ---- factorize 4x4 kernel (rank-1): c[b]=K[0][b], r[a]=K[a][0]/K[0][0]
    const float c0 = __ldg(ker + 0), c1 = __ldg(ker + 1);
    const float c2 = __ldg(ker + 2), c3 = __ldg(ker + 3);
    const float inv = 1.0f / c0;
    const float r1 = __ldg(ker + 4)  * inv;
    const float r2 = __ldg(ker + 8)  * inv;
    const float r3 = __ldg(ker + 12) * inv;
    // flipped taps
    const float hk0 = c3, hk1 = c2, hk2 = c1, hk3 = c0;
    const float vk0 = r3, vk1 = r2, vk2 = r1;           // vk3 == 1.0f

    const float* __restrict__ p = x   + (size_t)plane * (HH * WW);
    float*       __restrict__ q = out + (size_t)plane * (HH * WW) + y0 * WW + x0;

    const bool hasL = (x0 > 0);
    const bool hasR = (x0 + 4 < WW);

    // load one input row (zero-padded) + horizontal pass
    auto hrow = [&](int r) -> float4 {
        float2 L = make_float2(0.f, 0.f);
        float4 M = make_float4(0.f, 0.f, 0.f, 0.f);
        float  R = 0.f;
        if (r >= 0 && r < HH) {
            const float* row = p + r * WW;
            if (hasL) L = *reinterpret_cast<const float2*>(row + x0 - 2);
            M = *reinterpret_cast<const float4*>(row + x0);
            if (hasR) R = row[x0 + 4];
        }
        float4 h;
        h.x = fmaf(L.x, hk0, fmaf(L.y, hk1, fmaf(M.x, hk2, M.y * hk3)));
        h.y = fmaf(L.y, hk0, fmaf(M.x, hk1, fmaf(M.y, hk2, M.z * hk3)));
        h.z = fmaf(M.x, hk0, fmaf(M.y, hk1, fmaf(M.z, hk2, M.w * hk3)));
        h.w = fmaf(M.y, hk0, fmaf(M.z, hk1, fmaf(M.w, hk2, R   * hk3)));
        return h;
    };

    // rolling 4-row h window; emit one output row per new input row
    float4 h0 = hrow(y0 - 2);
    float4 h1 = hrow(y0 - 1);
    float4 h2 = hrow(y0);

    #pragma unroll
    for (int k = 0; k < TY; ++k) {
        float4 h3 = hrow(y0 + 1 + k);
        float4 a;
        a.x = fmaf(h0.x, vk0, fmaf(h1.x, vk1, fmaf(h2.x, vk2, h3.x)));
        a.y = fmaf(h0.y, vk0, fmaf(h1.y, vk1, fmaf(h2.y, vk2, h3.y)));
        a.z = fmaf(h0.z, vk0, fmaf(h1.z, vk1, fmaf(h2.z, vk2, h3.z)));
        a.w = fmaf(h0.w, vk0, fmaf(h1.w, vk1, fmaf(h2.w, vk2, h3.w)));
        *reinterpret_cast<float4*>(q + k * WW) = a;
        h0 = h1; h1 = h2; h2 = h3;
    }
}

extern "C" void kernel_launch(void* const* d_in, const int* in_sizes, int n_in,
                              void* d_out, int out_size)
{
    const float* x   = (const float*)d_in[0];
    const float* ker = (const float*)d_in[1];
    float*       out = (float*)d_out;

    const int planes = in_sizes[0] / (HH * WW);   // 8*256 = 2048
    dim3 block(32, 8);                            // 256 thr: full row x 8 y-threads
    dim3 grid(HH / 64, planes);                   // 2 strips x 2048 planes = 4096
    blur_kernel<<<grid, block>>>(x, ker, out);
}

// round 4
// speedup vs baseline: 1.1746x; 1.0802x over previous
#include <cuda_runtime.h>

#define HH 128
#define WW 128
#define TY 8    // output rows per thread (streamed)

struct Row { float2 L; float4 M; float R; };

// Depthwise 4x4 blur (upfirdn2d pad=(2,1)), separable rank-1 kernel.
// out[y] = vk0*h[y-2] + vk1*h[y-1] + vk2*h[y] + h[y+1]
// h[x]   = hk0*in[x-2] + hk1*in[x-1] + hk2*in[x] + hk3*in[x+1]
// Direct halo loads (L1-served), 1-row software prefetch, evict-first stores.
__global__ __launch_bounds__(256, 4) void blur_kernel(
    const float* __restrict__ x,
    const float* __restrict__ ker,
    float* __restrict__ out)
{
    const int plane = blockIdx.y;                       // (n,c) plane
    const int y0 = blockIdx.x * 64 + threadIdx.y * TY;  // 8-row output strip
    const int x0 = threadIdx.x * 4;                     // 4-col output block

    // ---- factorize 4x4 kernel (rank-1): c[b]=K[0][b], r[a]=K[a][0]/K[0][0]
    const float c0 = __ldg(ker + 0), c1 = __ldg(ker + 1);
    const float c2 = __ldg(ker + 2), c3 = __ldg(ker + 3);
    const float inv = 1.0f / c0;
    const float r1 = __ldg(ker + 4)  * inv;
    const float r2 = __ldg(ker + 8)  * inv;
    const float r3 = __ldg(ker + 12) * inv;
    const float hk0 = c3, hk1 = c2, hk2 = c1, hk3 = c0; // flipped taps
    const float vk0 = r3, vk1 = r2, vk2 = r1;           // vk3 == 1.0f

    const float* __restrict__ p = x   + (size_t)plane * (HH * WW);
    float*       __restrict__ q = out + (size_t)plane * (HH * WW) + y0 * WW + x0;

    const bool hasL = (x0 > 0);
    const bool hasR = (x0 + 4 < WW);

    auto ldrow = [&](int r) -> Row {
        Row v;
        v.L = make_float2(0.f, 0.f);
        v.M = make_float4(0.f, 0.f, 0.f, 0.f);
        v.R = 0.f;
        if (r >= 0 && r < HH) {
            const float* row = p + r * WW;
            if (hasL) v.L = *reinterpret_cast<const float2*>(row + x0 - 2);
            v.M = *reinterpret_cast<const float4*>(row + x0);
            if (hasR) v.R = row[x0 + 4];
        }
        return v;
    };
    auto hpass = [&](const Row& v) -> float4 {
        float4 h;
        h.x = fmaf(v.L.x, hk0, fmaf(v.L.y, hk1, fmaf(v.M.x, hk2, v.M.y * hk3)));
        h.y = fmaf(v.L.y, hk0, fmaf(v.M.x, hk1, fmaf(v.M.y, hk2, v.M.z * hk3)));
        h.z = fmaf(v.M.x, hk0, fmaf(v.M.y, hk1, fmaf(v.M.z, hk2, v.M.w * hk3)));
        h.w = fmaf(v.M.y, hk0, fmaf(v.M.z, hk1, fmaf(v.M.w, hk2, v.R   * hk3)));
        return h;
    };

    // prologue: 4 rows of loads issued before first use
    Row Ra = ldrow(y0 - 2);
    Row Rb = ldrow(y0 - 1);
    Row Rc = ldrow(y0);
    Row Rn = ldrow(y0 + 1);        // pipelined "next" row
    float4 h0 = hpass(Ra);
    float4 h1 = hpass(Rb);
    float4 h2 = hpass(Rc);

    #pragma unroll
    for (int k = 0; k < TY; ++k) {
        Row Rn2;
        if (k < TY - 1) Rn2 = ldrow(y0 + 2 + k);   // prefetch before consuming Rn
        float4 h3 = hpass(Rn);
        float4 a;
        a.x = fmaf(h0.x, vk0, fmaf(h1.x, vk1, fmaf(h2.x, vk2, h3.x)));
        a.y = fmaf(h0.y, vk0, fmaf(h1.y, vk1, fmaf(h2.y, vk2, h3.y)));
        a.z = fmaf(h0.z, vk0, fmaf(h1.z, vk1, fmaf(h2.z, vk2, h3.z)));
        a.w = fmaf(h0.w, vk0, fmaf(h1.w, vk1, fmaf(h2.w, vk2, h3.w)));
        __stcs(reinterpret_cast<float4*>(q + k * WW), a);  // evict-first: don't thrash L2
        h0 = h1; h1 = h2; h2 = h3;
        if (k < TY - 1) Rn = Rn2;
    }
}

extern "C" void kernel_launch(void* const* d_in, const int* in_sizes, int n_in,
                              void* d_out, int out_size)
{
    const float* x   = (const float*)d_in[0];
    const float* ker = (const float*)d_in[1];
    float*       out = (float*)d_out;

    const int planes = in_sizes[0] / (HH * WW);   // 8*256 = 2048
    dim3 block(32, 8);                            // 256 thr: full row x 8 y-threads
    dim3 grid(HH / 64, planes);                   // 2 strips x 2048 planes = 4096
    blur_kernel<<<grid, block>>>(x, ker, out);
}

// round 5
// speedup vs baseline: 1.2116x; 1.0315x over previous
#include <cuda_runtime.h>

#define HH 128
#define WW 128
#define TY 8    // output rows per thread (streamed)

// Depthwise 4x4 blur (upfirdn2d pad=(2,1)), separable rank-1 kernel.
// out[y] = vk0*h[y-2] + vk1*h[y-1] + vk2*h[y] + h[y+1]
// h[x]   = hk0*in[x-2] + hk1*in[x-1] + hk2*in[x] + hk3*in[x+1]
// One float4 LDG per row per thread; x-halos via SHFL on prefetched data
// (load issued one iteration ahead, so the shfl never waits on memory).
__global__ __launch_bounds__(256, 5) void blur_kernel(
    const float* __restrict__ x,
    const float* __restrict__ ker,
    float* __restrict__ out)
{
    const int plane = blockIdx.y;                       // (n,c) plane
    const int y0 = blockIdx.x * 64 + threadIdx.y * TY;  // 8-row output strip
    const int lane = threadIdx.x;                       // warp == one full row
    const int x0 = lane * 4;

    // ---- factorize 4x4 kernel (rank-1): c[b]=K[0][b], r[a]=K[a][0]/K[0][0]
    const float c0 = __ldg(ker + 0), c1 = __ldg(ker + 1);
    const float c2 = __ldg(ker + 2), c3 = __ldg(ker + 3);
    const float inv = 1.0f / c0;
    const float r1 = __ldg(ker + 4)  * inv;
    const float r2 = __ldg(ker + 8)  * inv;
    const float r3 = __ldg(ker + 12) * inv;
    const float hk0 = c3, hk1 = c2, hk2 = c1, hk3 = c0; // flipped taps
    const float vk0 = r3, vk1 = r2, vk2 = r1;           // vk3 == 1.0f

    const float* __restrict__ p = x   + (size_t)plane * (HH * WW);
    float*       __restrict__ q = out + (size_t)plane * (HH * WW) + y0 * WW + x0;

    // load one row's float4 (zero outside the image)
    auto ldrow = [&](int r) -> float4 {
        float4 M = make_float4(0.f, 0.f, 0.f, 0.f);
        if (r >= 0 && r < HH)                           // warp-uniform predicate
            M = *reinterpret_cast<const float4*>(p + r * WW + x0);
        return M;
    };
    // horizontal pass; halos from neighbor lanes (data already in registers)
    auto hpass = [&](const float4& M) -> float4 {
        float lm2 = __shfl_up_sync(0xffffffffu, M.z, 1);    // in[x0-2]
        float lm1 = __shfl_up_sync(0xffffffffu, M.w, 1);    // in[x0-1]
        float rp0 = __shfl_down_sync(0xffffffffu, M.x, 1);  // in[x0+4]
        if (lane == 0)  { lm2 = 0.f; lm1 = 0.f; }           // left pad (2 zeros)
        if (lane == 31) { rp0 = 0.f; }                      // right pad (1 zero)
        float4 h;
        h.x = fmaf(lm2, hk0, fmaf(lm1, hk1, fmaf(M.x, hk2, M.y * hk3)));
        h.y = fmaf(lm1, hk0, fmaf(M.x, hk1, fmaf(M.y, hk2, M.z * hk3)));
        h.z = fmaf(M.x, hk0, fmaf(M.y, hk1, fmaf(M.z, hk2, M.w * hk3)));
        h.w = fmaf(M.y, hk0, fmaf(M.z, hk1, fmaf(M.w, hk2, rp0 * hk3)));
        return h;
    };

    // prologue: 4 rows of loads in flight before first use
    float4 Ra = ldrow(y0 - 2);
    float4 Rb = ldrow(y0 - 1);
    float4 Rc = ldrow(y0);
    float4 Rn = ldrow(y0 + 1);     // pipelined "next" row
    float4 h0 = hpass(Ra);
    float4 h1 = hpass(Rb);
    float4 h2 = hpass(Rc);

    #pragma unroll
    for (int k = 0; k < TY; ++k) {
        float4 Rn2;
        if (k < TY - 1) Rn2 = ldrow(y0 + 2 + k);   // prefetch before consuming Rn
        float4 h3 = hpass(Rn);
        float4 a;
        a.x = fmaf(h0.x, vk0, fmaf(h1.x, vk1, fmaf(h2.x, vk2, h3.x)));
        a.y = fmaf(h0.y, vk0, fmaf(h1.y, vk1, fmaf(h2.y, vk2, h3.y)));
        a.z = fmaf(h0.z, vk0, fmaf(h1.z, vk1, fmaf(h2.z, vk2, h3.z)));
        a.w = fmaf(h0.w, vk0, fmaf(h1.w, vk1, fmaf(h2.w, vk2, h3.w)));
        __stcs(reinterpret_cast<float4*>(q + k * WW), a);  // evict-first stores
        h0 = h1; h1 = h2; h2 = h3;
        if (k < TY - 1) Rn = Rn2;
    }
}

extern "C" void kernel_launch(void* const* d_in, const int* in_sizes, int n_in,
                              void* d_out, int out_size)
{
    const float* x   = (const float*)d_in[0];
    const float* ker = (const float*)d_in[1];
    float*       out = (float*)d_out;

    const int planes = in_sizes[0] / (HH * WW);   // 8*256 = 2048
    dim3 block(32, 8);                            // 256 thr: full row x 8 y-threads
    dim3 grid(HH / 64, planes);                   // 2 strips x 2048 planes = 4096
    blur_kernel<<<grid, block>>>(x, ker, out);
}

// round 7
// speedup vs baseline: 1.2193x; 1.0063x over previous
#include <cuda_runtime.h>

#define HH 128
#define WW 128
#define TY 8    // output rows per thread (streamed)

// Depthwise 4x4 blur (upfirdn2d pad=(2,1)), separable rank-1 kernel.
// out[y] = vk0*h[y-2] + vk1*h[y-1] + vk2*h[y] + h[y+1]
// h[x]   = hk0*in[x-2] + hk1*in[x-1] + hk2*in[x] + hk3*in[x+1]
// One float4 LDG per row per thread; x-halos via SHFL on prefetched data.
// Depth-2 software pipeline: each row's load issues 2 iterations before use.
__global__ __launch_bounds__(256, 5) void blur_kernel(
    const float* __restrict__ x,
    const float* __restrict__ ker,
    float* __restrict__ out)
{
    const int plane = blockIdx.y;                       // (n,c) plane
    const int y0 = blockIdx.x * 64 + threadIdx.y * TY;  // 8-row output strip
    const int lane = threadIdx.x;                       // warp == one full row
    const int x0 = lane * 4;

    // ---- factorize 4x4 kernel (rank-1): c[b]=K[0][b], r[a]=K[a][0]/K[0][0]
    const float c0 = __ldg(ker + 0), c1 = __ldg(ker + 1);
    const float c2 = __ldg(ker + 2), c3 = __ldg(ker + 3);
    const float inv = 1.0f / c0;
    const float r1 = __ldg(ker + 4)  * inv;
    const float r2 = __ldg(ker + 8)  * inv;
    const float r3 = __ldg(ker + 12) * inv;
    const float hk0 = c3, hk1 = c2, hk2 = c1, hk3 = c0; // flipped taps
    const float vk0 = r3, vk1 = r2, vk2 = r1;           // vk3 == 1.0f

    const float* __restrict__ p = x   + (size_t)plane * (HH * WW);
    float*       __restrict__ q = out + (size_t)plane * (HH * WW) + y0 * WW + x0;

    auto ldrow = [&](int r) -> float4 {
        float4 M = make_float4(0.f, 0.f, 0.f, 0.f);
        if (r >= 0 && r < HH)                           // warp-uniform predicate
            M = *reinterpret_cast<const float4*>(p + r * WW + x0);
        return M;
    };
    auto hpass = [&](const float4& M) -> float4 {
        float lm2 = __shfl_up_sync(0xffffffffu, M.z, 1);    // in[x0-2]
        float lm1 = __shfl_up_sync(0xffffffffu, M.w, 1);    // in[x0-1]
        float rp0 = __shfl_down_sync(0xffffffffu, M.x, 1);  // in[x0+4]
        if (lane == 0)  { lm2 = 0.f; lm1 = 0.f; }           // left pad (2 zeros)
        if (lane == 31) { rp0 = 0.f; }                      // right pad (1 zero)
        float4 h;
        h.x = fmaf(lm2, hk0, fmaf(lm1, hk1, fmaf(M.x, hk2, M.y * hk3)));
        h.y = fmaf(lm1, hk0, fmaf(M.x, hk1, fmaf(M.y, hk2, M.z * hk3)));
        h.z = fmaf(M.x, hk0, fmaf(M.y, hk1, fmaf(M.z, hk2, M.w * hk3)));
        h.w = fmaf(M.y, hk0, fmaf(M.z, hk1, fmaf(M.w, hk2, rp0 * hk3)));
        return h;
    };

    // prologue: rows y0-2..y0+2 issued before any use; Rn/Rn1 = 2-deep pipeline
    float4 Ra  = ldrow(y0 - 2);
    float4 Rb  = ldrow(y0 - 1);
    float4 Rc  = ldrow(y0);
    float4 Rn  = ldrow(y0 + 1);    // used at k=0
    float4 Rn1 = ldrow(y0 + 2);    // used at k=1
    float4 h0 = hpass(Ra);
    float4 h1 = hpass(Rb);
    float4 h2 = hpass(Rc);

    #pragma unroll
    for (int k = 0; k < TY; ++k) {
        float4 h3 = hpass(Rn);                  // consume oldest in-flight row
        Rn = Rn1;                               // rotate pipeline
        if (k < TY - 2) Rn1 = ldrow(y0 + 3 + k);// issue 2 iterations ahead of use
        float4 a;
        a.x = fmaf(h0.x, vk0, fmaf(h1.x, vk1, fmaf(h2.x, vk2, h3.x)));
        a.y = fmaf(h0.y, vk0, fmaf(h1.y, vk1, fmaf(h2.y, vk2, h3.y)));
        a.z = fmaf(h0.z, vk0, fmaf(h1.z, vk1, fmaf(h2.z, vk2, h3.z)));
        a.w = fmaf(h0.w, vk0, fmaf(h1.w, vk1, fmaf(h2.w, vk2, h3.w)));
        __stcs(reinterpret_cast<float4*>(q + k * WW), a);  // evict-first stores
        h0 = h1; h1 = h2; h2 = h3;
    }
}

extern "C" void kernel_launch(void* const* d_in, const int* in_sizes, int n_in,
                              void* d_out, int out_size)
{
    const float* x   = (const float*)d_in[0];
    const float* ker = (const float*)d_in[1];
    float*       out = (float*)d_out;

    const int planes = in_sizes[0] / (HH * WW);   // 8*256 = 2048
    dim3 block(32, 8);                            // 256 thr: full row x 8 y-threads
    dim3 grid(HH / 64, planes);                   // 2 strips x 2048 planes = 4096
    blur_kernel<<<grid, block>>>(x, ker, out);
}